// round 3
// baseline (speedup 1.0000x reference)
#include <cuda_runtime.h>
#include <math.h>

#define NB 64
#define NN 1024
#define NF 3
#define NH 64
#define NT 32

// ---------------- scratch (static device memory; no runtime allocation) ----
__device__ float g_P1[NB * NN * NH];        // h1 @ W2^T          (16 MB)
__device__ float g_P2[NB * NN * NH];        // h2 @ W3^T          (16 MB)
__device__ float g_spart[NB * 32 * NN];     // per-block colsum partials (8 MB)
__device__ float g_s[NB * NN];              // colsum(A) per chunk
__device__ float g_crep[NB * NH];           // chunk representations
__device__ float g_xw[2 * NB * 4 * NT];     // LSTM input projections [dir][t][128]
__device__ float g_tvec[NH];                // ns1_right @ time_repr + ns1_b
__device__ float g_embp[4 * NN * NH];       // split-K partials of node_emb[pidx]

__device__ __forceinline__ float sigm(float x) { return 1.0f / (1.0f + expf(-x)); }

// ============================================================================
// K1: layer 1 fused:  y = A@X (F=3) ; h1 = relu(y@W1^T + b1) ; P1 = h1@W2^T
//     + per-block column-sum partials of A (for the chunk_repr trick).
// grid (32 rowblocks, 64 chunks), 256 threads, warp-per-row (4 rows/warp).
// ============================================================================
__global__ __launch_bounds__(256) void k_gcn1(
    const float* __restrict__ feat, const float* __restrict__ adj,
    const float* __restrict__ w1, const float* __restrict__ b1,
    const float* __restrict__ w2)
{
    __shared__ float Xs0[NN], Xs1[NN], Xs2[NN];
    __shared__ float w1s[NH * 3];
    __shared__ float b1s[NH];
    __shared__ float W2t[NH * NH];   // W2t[o][o'] = w2[o'*64 + o]
    __shared__ float colp[NN];
    __shared__ float hs[8][NH];

    const int b = blockIdx.y;
    const int tid = threadIdx.x;

    const float* fb = feat + (size_t)b * NN * NF;
    for (int idx = tid; idx < NN * NF; idx += 256) {
        int j = idx / 3, f = idx % 3;
        float v = fb[idx];
        if (f == 0) Xs0[j] = v; else if (f == 1) Xs1[j] = v; else Xs2[j] = v;
    }
    for (int idx = tid; idx < NH * 3; idx += 256) w1s[idx] = w1[idx];
    if (tid < NH) b1s[tid] = b1[tid];
    for (int idx = tid; idx < NH * NH; idx += 256) {
        int o = idx >> 6, op = idx & 63;
        W2t[idx] = w2[op * NH + o];
    }
    for (int idx = tid; idx < NN; idx += 256) colp[idx] = 0.0f;
    __syncthreads();

    const int w = tid >> 5, L = tid & 31;

    float4 ca[8];
#pragma unroll
    for (int t = 0; t < 8; t++) ca[t] = make_float4(0.f, 0.f, 0.f, 0.f);

    for (int r = 0; r < 4; r++) {
        const int i = blockIdx.x * 32 + w * 4 + r;
        const float4* arow = (const float4*)(adj + ((size_t)b * NN + i) * NN);
        float y0 = 0.f, y1 = 0.f, y2 = 0.f;
#pragma unroll
        for (int t = 0; t < 8; t++) {
            float4 a = arow[t * 32 + L];
            int j = t * 128 + L * 4;
            ca[t].x += a.x; ca[t].y += a.y; ca[t].z += a.z; ca[t].w += a.w;
            y0 += a.x * Xs0[j] + a.y * Xs0[j + 1] + a.z * Xs0[j + 2] + a.w * Xs0[j + 3];
            y1 += a.x * Xs1[j] + a.y * Xs1[j + 1] + a.z * Xs1[j + 2] + a.w * Xs1[j + 3];
            y2 += a.x * Xs2[j] + a.y * Xs2[j + 1] + a.z * Xs2[j + 2] + a.w * Xs2[j + 3];
        }
#pragma unroll
        for (int off = 16; off; off >>= 1) {
            y0 += __shfl_xor_sync(0xffffffffu, y0, off);
            y1 += __shfl_xor_sync(0xffffffffu, y1, off);
            y2 += __shfl_xor_sync(0xffffffffu, y2, off);
        }
        // h1 for outputs L and L+32
        float hA = fmaxf(y0 * w1s[L * 3] + y1 * w1s[L * 3 + 1] + y2 * w1s[L * 3 + 2] + b1s[L], 0.f);
        int L2 = L + 32;
        float hB = fmaxf(y0 * w1s[L2 * 3] + y1 * w1s[L2 * 3 + 1] + y2 * w1s[L2 * 3 + 2] + b1s[L2], 0.f);
        hs[w][L] = hA; hs[w][L2] = hB;
        __syncwarp();
        float p0 = 0.f, p1 = 0.f;
#pragma unroll
        for (int o = 0; o < NH; o++) {
            float hv = hs[w][o];
            p0 += hv * W2t[o * NH + L];
            p1 += hv * W2t[o * NH + L2];
        }
        size_t po = ((size_t)b * NN + i) * NH;
        g_P1[po + L] = p0;
        g_P1[po + L2] = p1;
        __syncwarp();
    }

    // deterministic in-block column-sum combine (serialized over warps)
    for (int ws = 0; ws < 8; ws++) {
        if (w == ws) {
#pragma unroll
            for (int t = 0; t < 8; t++) {
                int j = t * 128 + L * 4;
                colp[j]     += ca[t].x;
                colp[j + 1] += ca[t].y;
                colp[j + 2] += ca[t].z;
                colp[j + 3] += ca[t].w;
            }
        }
        __syncthreads();
    }
    for (int idx = tid; idx < NN; idx += 256)
        g_spart[((size_t)b * 32 + blockIdx.x) * NN + idx] = colp[idx];
}

// colsum reduction: s[b][j] = sum over 32 block partials
__global__ void k_sred()
{
    int b = blockIdx.y;
    int j = blockIdx.x * 256 + threadIdx.x;
    float acc = 0.f;
#pragma unroll
    for (int p = 0; p < 32; p++) acc += g_spart[((size_t)b * 32 + p) * NN + j];
    g_s[b * NN + j] = acc;
}

// ============================================================================
// K2: layer 2:  C = relu(A @ P1 + b2) ; P2 = C @ W3^T
// Tiled fp32 GEMM, BM=64 BN=64 BK=16, 256 threads, 4x4 microtile,
// W3 epilogue done in-block through shared memory.
// STATIC shared memory: 8192 floats = 32768 B  (2 CTAs/SM).
// grid (16 rowblocks, 64 chunks).
// ============================================================================
__global__ __launch_bounds__(256) void k_gcn2(
    const float* __restrict__ adj, const float* __restrict__ b2,
    const float* __restrict__ w3)
{
    __shared__ float sm[8192];
    float* As  = sm;                 // [16][68] = 1088 (mainloop only)
    float* Bs  = sm + 1088;          // [16][64] = 1024 (mainloop only)
    float* Cs  = sm;                 // [64][64] = 4096 (epilogue, reuses As/Bs)
    float* W3t = sm + 4096;          // [64][64]  W3t[o][o'] = w3[o'*64+o]

    const int b = blockIdx.y;
    const int tid = threadIdx.x;
    const int tx = tid & 15, ty = tid >> 4;
    const int m0 = blockIdx.x * 64;

    for (int idx = tid; idx < 4096; idx += 256) {
        int o = idx >> 6, op = idx & 63;
        W3t[idx] = w3[op * 64 + o];
    }

    const float* Ab = adj + ((size_t)b << 20);
    const float* Pb = g_P1 + (size_t)b * NN * NH;

    float acc[4][4];
#pragma unroll
    for (int i = 0; i < 4; i++)
#pragma unroll
        for (int j = 0; j < 4; j++) acc[i][j] = 0.f;

    const int arow_ = tid >> 2, akq = tid & 3;
    const int brow = tid >> 4, bc4 = tid & 15;

    for (int kt = 0; kt < 64; kt++) {
        const int k0 = kt * 16;
        float4 a = *(const float4*)(Ab + (size_t)(m0 + arow_) * NN + k0 + akq * 4);
        As[(akq * 4 + 0) * 68 + arow_] = a.x;
        As[(akq * 4 + 1) * 68 + arow_] = a.y;
        As[(akq * 4 + 2) * 68 + arow_] = a.z;
        As[(akq * 4 + 3) * 68 + arow_] = a.w;
        *(float4*)(Bs + brow * 64 + bc4 * 4) =
            *(const float4*)(Pb + (size_t)(k0 + brow) * NH + bc4 * 4);
        __syncthreads();
#pragma unroll
        for (int kk = 0; kk < 16; kk++) {
            float4 a4 = *(const float4*)(As + kk * 68 + ty * 4);
            float4 b4 = *(const float4*)(Bs + kk * 64 + tx * 4);
            float av[4] = {a4.x, a4.y, a4.z, a4.w};
#pragma unroll
            for (int i = 0; i < 4; i++) {
                acc[i][0] += av[i] * b4.x;
                acc[i][1] += av[i] * b4.y;
                acc[i][2] += av[i] * b4.z;
                acc[i][3] += av[i] * b4.w;
            }
        }
        __syncthreads();
    }

    // epilogue: bias + relu -> Cs  (bias straight from L2, 1 float4/thread)
    float4 bb = *(const float4*)(b2 + tx * 4);
#pragma unroll
    for (int i = 0; i < 4; i++) {
        int row = ty * 4 + i;
        Cs[row * 64 + tx * 4 + 0] = fmaxf(acc[i][0] + bb.x, 0.f);
        Cs[row * 64 + tx * 4 + 1] = fmaxf(acc[i][1] + bb.y, 0.f);
        Cs[row * 64 + tx * 4 + 2] = fmaxf(acc[i][2] + bb.z, 0.f);
        Cs[row * 64 + tx * 4 + 3] = fmaxf(acc[i][3] + bb.w, 0.f);
    }
    __syncthreads();

    float acc2[4][4];
#pragma unroll
    for (int i = 0; i < 4; i++)
#pragma unroll
        for (int j = 0; j < 4; j++) acc2[i][j] = 0.f;

#pragma unroll 4
    for (int o = 0; o < 64; o++) {
        float4 w4 = *(const float4*)(W3t + o * 64 + tx * 4);
#pragma unroll
        for (int i = 0; i < 4; i++) {
            float cv = Cs[(ty * 4 + i) * 64 + o];
            acc2[i][0] += cv * w4.x;
            acc2[i][1] += cv * w4.y;
            acc2[i][2] += cv * w4.z;
            acc2[i][3] += cv * w4.w;
        }
    }
#pragma unroll
    for (int i = 0; i < 4; i++) {
        int row = m0 + ty * 4 + i;
        float4 p = make_float4(acc2[i][0], acc2[i][1], acc2[i][2], acc2[i][3]);
        *(float4*)(g_P2 + ((size_t)b * NN + row) * NH + tx * 4) = p;
    }
}

// ============================================================================
// chunk_repr[b][o] = (1/N) * sum_j s[b][j]*P2[b][j][o] + b3[o]
// ============================================================================
__global__ void k_crep(const float* __restrict__ b3)
{
    __shared__ float red[256];
    const int b = blockIdx.x;
    const int tid = threadIdx.x;
    const int o = tid & 63, part = tid >> 6;
    const float* sb = g_s + b * NN;
    const float* Pb = g_P2 + (size_t)b * NN * NH;
    float acc = 0.f;
    for (int j = part * 256; j < part * 256 + 256; j++)
        acc += sb[j] * Pb[(size_t)j * NH + o];
    red[tid] = acc;
    __syncthreads();
    if (part == 0) {
        float tot = red[o] + red[64 + o] + red[128 + o] + red[192 + o];
        g_crep[b * NH + o] = tot * (1.0f / NN) + b3[o];
    }
}

// LSTM input projections: xw[dir][t][g] = crep[t] . wih[g] + bih[g] + bhh[g]
__global__ void k_xw(const float* __restrict__ wihf, const float* __restrict__ bihf,
                     const float* __restrict__ bhhf,
                     const float* __restrict__ wihb, const float* __restrict__ bihb,
                     const float* __restrict__ bhhb)
{
    __shared__ float cr[64];
    const int t = blockIdx.x;
    const int tid = threadIdx.x;
    if (tid < 64) cr[tid] = g_crep[t * 64 + tid];
    __syncthreads();
    const int g = tid & 127, dir = tid >> 7;
    const float* wih = dir ? wihb : wihf;
    float acc = dir ? (bihb[g] + bhhb[g]) : (bihf[g] + bhhf[g]);
    const float* wg = wih + g * 64;
#pragma unroll
    for (int k = 0; k < 64; k++) acc += cr[k] * wg[k];
    g_xw[dir * 8192 + t * 128 + g] = acc;
}

// ============================================================================
// BiLSTM scan (both directions in one block) + time encoder + tvec precompute
// ============================================================================
__global__ __launch_bounds__(256) void k_lstm(
    const float* __restrict__ whhf, const float* __restrict__ whhb,
    const float* __restrict__ tew, const float* __restrict__ teb,
    const float* __restrict__ ns1w, const float* __restrict__ ns1b)
{
    __shared__ float whTf[32 * 128], whTb[32 * 128];  // [k][g]
    __shared__ float zf[128], zb[128];
    __shared__ float hf[32], cf[32], hb[32], cb[32], sf_[32], sb_[32], tr[64];
    const int tid = threadIdx.x;

    for (int idx = tid; idx < 4096; idx += 256) {
        int k = idx >> 7, g = idx & 127;
        whTf[idx] = whhf[g * 32 + k];
        whTb[idx] = whhb[g * 32 + k];
    }
    if (tid < 32) { hf[tid] = 0.f; cf[tid] = 0.f; hb[tid] = 0.f; cb[tid] = 0.f; sf_[tid] = 0.f; sb_[tid] = 0.f; }
    __syncthreads();

    for (int st = 0; st < 64; st++) {
        if (tid < 128) {
            const int g = tid;
            float z = g_xw[st * 128 + g];
#pragma unroll
            for (int k = 0; k < 32; k++) z += hf[k] * whTf[k * 128 + g];
            zf[g] = z;
        } else {
            const int g = tid - 128;
            float z = g_xw[8192 + (63 - st) * 128 + g];
#pragma unroll
            for (int k = 0; k < 32; k++) z += hb[k] * whTb[k * 128 + g];
            zb[g] = z;
        }
        __syncthreads();
        if (tid < 32) {
            int j = tid;
            float iv = sigm(zf[j]), fv = sigm(zf[32 + j]);
            float gv = tanhf(zf[64 + j]), ov = sigm(zf[96 + j]);
            float c = fv * cf[j] + iv * gv;
            cf[j] = c;
            float h = ov * tanhf(c);
            hf[j] = h; sf_[j] += h;
        } else if (tid >= 128 && tid < 160) {
            int j = tid - 128;
            float iv = sigm(zb[j]), fv = sigm(zb[32 + j]);
            float gv = tanhf(zb[64 + j]), ov = sigm(zb[96 + j]);
            float c = fv * cb[j] + iv * gv;
            cb[j] = c;
            float h = ov * tanhf(c);
            hb[j] = h; sb_[j] += h;
        }
        __syncthreads();
    }

    if (tid < 64) {
        float acc = teb[tid];
        const float* tw = tew + tid * 64;
#pragma unroll
        for (int k = 0; k < 32; k++) acc += (sf_[k] * (1.0f / 64)) * tw[k];
#pragma unroll
        for (int k = 0; k < 32; k++) acc += (sb_[k] * (1.0f / 64)) * tw[32 + k];
        tr[tid] = fmaxf(acc, 0.f);
    }
    __syncthreads();
    if (tid < 64) {
        float acc = ns1b[tid];
        const float* nw = ns1w + tid * 128 + 64;  // right half (time part)
#pragma unroll
        for (int k = 0; k < 64; k++) acc += tr[k] * nw[k];
        g_tvec[tid] = acc;
    }
}

// ============================================================================
// K3a: node_emb for the predicted chunk only: embp[ks] += A[pidx] @ P2[pidx]
// split-K x4, BM=64, BN=64, BK=16, deterministic per-split partial stores.
// ============================================================================
__global__ __launch_bounds__(256) void k_gcn3(
    const float* __restrict__ adj, const int* __restrict__ pidx)
{
    __shared__ float As[16 * 68];
    __shared__ float Bs[16 * 64];
    const int chunk = pidx[0];
    const float* Ab = adj + ((size_t)chunk << 20);
    const float* Pb = g_P2 + (size_t)chunk * NN * NH;
    const int m0 = blockIdx.x * 64;
    const int kb = blockIdx.y * 256;
    const int tid = threadIdx.x;
    const int tx = tid & 15, ty = tid >> 4;
    const int arow = tid >> 2, akq = tid & 3;
    const int brow = tid >> 4, bc4 = tid & 15;

    float acc[4][4];
#pragma unroll
    for (int i = 0; i < 4; i++)
#pragma unroll
        for (int j = 0; j < 4; j++) acc[i][j] = 0.f;

    for (int kt = 0; kt < 16; kt++) {
        const int k0 = kb + kt * 16;
        float4 a = *(const float4*)(Ab + (size_t)(m0 + arow) * NN + k0 + akq * 4);
        As[(akq * 4 + 0) * 68 + arow] = a.x;
        As[(akq * 4 + 1) * 68 + arow] = a.y;
        As[(akq * 4 + 2) * 68 + arow] = a.z;
        As[(akq * 4 + 3) * 68 + arow] = a.w;
        *(float4*)(Bs + brow * 64 + bc4 * 4) =
            *(const float4*)(Pb + (size_t)(k0 + brow) * NH + bc4 * 4);
        __syncthreads();
#pragma unroll
        for (int kk = 0; kk < 16; kk++) {
            float4 a4 = *(const float4*)(As + kk * 68 + ty * 4);
            float4 b4 = *(const float4*)(Bs + kk * 64 + tx * 4);
            float av[4] = {a4.x, a4.y, a4.z, a4.w};
#pragma unroll
            for (int i = 0; i < 4; i++) {
                acc[i][0] += av[i] * b4.x;
                acc[i][1] += av[i] * b4.y;
                acc[i][2] += av[i] * b4.z;
                acc[i][3] += av[i] * b4.w;
            }
        }
        __syncthreads();
    }
#pragma unroll
    for (int i = 0; i < 4; i++)
#pragma unroll
        for (int j = 0; j < 4; j++)
            g_embp[(size_t)blockIdx.y * (NN * NH) + (m0 + ty * 4 + i) * NH + tx * 4 + j] = acc[i][j];
}

// ============================================================================
// K3b: node scorer: h = relu([emb, time_repr] @ ns1^T + b) ; score = sigmoid(h @ ns2^T + b)
// warp-per-row; tvec already holds the time_repr contribution + ns1_b.
// ============================================================================
__global__ __launch_bounds__(256) void k_score(
    const float* __restrict__ b3, const float* __restrict__ ns1w,
    const float* __restrict__ ns2w, const float* __restrict__ ns2b,
    float* __restrict__ out)
{
    __shared__ float WLt[64 * 64];  // WLt[k][o] = ns1w[o*128 + k]  (left half)
    __shared__ float ns2s[64], tvs[64], b3s[64];
    __shared__ float ers[8][64];
    const int tid = threadIdx.x;
    for (int idx = tid; idx < 4096; idx += 256) {
        int k = idx >> 6, o = idx & 63;
        WLt[idx] = ns1w[o * 128 + k];
    }
    if (tid < 64) { ns2s[tid] = ns2w[tid]; tvs[tid] = g_tvec[tid]; b3s[tid] = b3[tid]; }
    __syncthreads();

    const int w = tid >> 5, L = tid & 31;
    const int row = blockIdx.x * 8 + w;
    ers[w][L] = g_embp[row * NH + L] + g_embp[65536 + row * NH + L]
              + g_embp[131072 + row * NH + L] + g_embp[196608 + row * NH + L] + b3s[L];
    int L2 = L + 32;
    ers[w][L2] = g_embp[row * NH + L2] + g_embp[65536 + row * NH + L2]
               + g_embp[131072 + row * NH + L2] + g_embp[196608 + row * NH + L2] + b3s[L2];
    __syncwarp();

    float a0 = tvs[L], a1 = tvs[L2];
#pragma unroll
    for (int k = 0; k < 64; k++) {
        float ev = ers[w][k];
        a0 += ev * WLt[k * 64 + L];
        a1 += ev * WLt[k * 64 + L2];
    }
    a0 = fmaxf(a0, 0.f);
    a1 = fmaxf(a1, 0.f);
    float p = a0 * ns2s[L] + a1 * ns2s[L2];
#pragma unroll
    for (int off = 16; off; off >>= 1) p += __shfl_xor_sync(0xffffffffu, p, off);
    if (L == 0) out[row] = 1.0f / (1.0f + expf(-(p + ns2b[0])));
}

// ============================================================================
extern "C" void kernel_launch(void* const* d_in, const int* in_sizes, int n_in,
                              void* d_out, int out_size)
{
    const float* feat  = (const float*)d_in[0];
    const float* adj   = (const float*)d_in[1];
    const float* gc1w  = (const float*)d_in[2];
    const float* gc1b  = (const float*)d_in[3];
    const float* gc2w  = (const float*)d_in[4];
    const float* gc2b  = (const float*)d_in[5];
    const float* gc3w  = (const float*)d_in[6];
    const float* gc3b  = (const float*)d_in[7];
    const float* wihf  = (const float*)d_in[8];
    const float* whhf  = (const float*)d_in[9];
    const float* bihf  = (const float*)d_in[10];
    const float* bhhf  = (const float*)d_in[11];
    const float* wihb  = (const float*)d_in[12];
    const float* whhb  = (const float*)d_in[13];
    const float* bihb  = (const float*)d_in[14];
    const float* bhhb  = (const float*)d_in[15];
    const float* tew   = (const float*)d_in[16];
    const float* teb   = (const float*)d_in[17];
    const float* ns1w  = (const float*)d_in[18];
    const float* ns1b  = (const float*)d_in[19];
    const float* ns2w  = (const float*)d_in[20];
    const float* ns2b  = (const float*)d_in[21];
    const int*   pidx  = (const int*)d_in[23];
    float* out = (float*)d_out;

    k_gcn1<<<dim3(32, 64), 256>>>(feat, adj, gc1w, gc1b, gc2w);
    k_sred<<<dim3(4, 64), 256>>>();
    k_gcn2<<<dim3(16, 64), 256>>>(adj, gc2b, gc3w);
    k_crep<<<64, 256>>>(gc3b);
    k_xw<<<64, 256>>>(wihf, bihf, bhhf, wihb, bihb, bhhb);
    k_lstm<<<1, 256>>>(whhf, whhb, tew, teb, ns1w, ns1b);
    k_gcn3<<<dim3(16, 4), 256>>>(adj, pidx);
    k_score<<<128, 256>>>(gc3b, ns1w, ns2w, ns2b, out);
}

// round 6
// speedup vs baseline: 1.5670x; 1.5670x over previous
#include <cuda_runtime.h>
#include <math.h>
#include <stdint.h>

#define NB 64
#define NN 1024
#define NF 3
#define NH 64
#define NT 32

// ---------------- scratch (static device memory) ---------------------------
__device__ float g_P1t[NB * NH * NN];       // P1 transposed [b][o][k]  (16 MB)
__device__ float g_P2[NB * NN * NH];        // C = relu(A@P1+b2)        (16 MB)
__device__ float g_spart[NB * 32 * NN];     // per-block colsum partials (8 MB)
__device__ float g_s[NB * NN];              // colsum(A) per chunk
__device__ float g_cpart[NB * 4 * NH];      // crep partials
__device__ float g_crep[NB * NH];           // chunk representations
__device__ float g_xw[2 * NB * 4 * NT];     // LSTM input projections
__device__ float g_tvec[NH];                // ns1_right @ time_repr + ns1_b
__device__ float g_embp[4 * NN * NH];       // split-K partials of A_p @ C_p

__device__ __forceinline__ float sigm(float x) { return 1.0f / (1.0f + expf(-x)); }

#define CP16(dst, src)  asm volatile("cp.async.cg.shared.global [%0], [%1], 16;" :: "r"(dst), "l"(src))
#define CP_COMMIT()     asm volatile("cp.async.commit_group;" ::: "memory")

__device__ __forceinline__ uint32_t smem_u32(const void* p) {
    uint32_t a;
    asm("{ .reg .u64 t; cvta.to.shared.u64 t, %1; cvt.u32.u64 %0, t; }" : "=r"(a) : "l"(p));
    return a;
}

// mma.sync m16n8k8 tf32 (legacy tensor path, baseline PTX, sm_80+)
__device__ __forceinline__ void mma1688(float* c, uint32_t a0, uint32_t a1,
                                        uint32_t a2, uint32_t a3,
                                        uint32_t b0, uint32_t b1) {
    asm volatile(
        "mma.sync.aligned.m16n8k8.row.col.f32.tf32.tf32.f32 "
        "{%0,%1,%2,%3}, {%4,%5,%6,%7}, {%8,%9}, {%0,%1,%2,%3};"
        : "+f"(c[0]), "+f"(c[1]), "+f"(c[2]), "+f"(c[3])
        : "r"(a0), "r"(a1), "r"(a2), "r"(a3), "r"(b0), "r"(b1));
}

// ============================================================================
// K1: y = A@X (F=3); h1 = relu(y@W1^T+b1); P1t[o][k] = (h1@W2^T)^T
//     + per-block colsum partials of A.
// ============================================================================
__global__ __launch_bounds__(256) void k_gcn1(
    const float* __restrict__ feat, const float* __restrict__ adj,
    const float* __restrict__ w1, const float* __restrict__ b1,
    const float* __restrict__ w2)
{
    __shared__ float Xs0[NN], Xs1[NN], Xs2[NN];
    __shared__ float w1s[NH * 3];
    __shared__ float b1s[NH];
    __shared__ float W2t[NH * NH];
    __shared__ float colp[NN];
    __shared__ float hs[8][NH];
    __shared__ float Pts[64][33];

    const int b = blockIdx.y;
    const int tid = threadIdx.x;

    const float* fb = feat + (size_t)b * NN * NF;
    for (int idx = tid; idx < NN * NF; idx += 256) {
        int j = idx / 3, f = idx % 3;
        float v = fb[idx];
        if (f == 0) Xs0[j] = v; else if (f == 1) Xs1[j] = v; else Xs2[j] = v;
    }
    for (int idx = tid; idx < NH * 3; idx += 256) w1s[idx] = w1[idx];
    if (tid < NH) b1s[tid] = b1[tid];
    for (int idx = tid; idx < NH * NH; idx += 256) {
        int o = idx >> 6, op = idx & 63;
        W2t[idx] = w2[op * NH + o];
    }
    for (int idx = tid; idx < NN; idx += 256) colp[idx] = 0.0f;
    __syncthreads();

    const int w = tid >> 5, L = tid & 31;

    float4 ca[8];
#pragma unroll
    for (int t = 0; t < 8; t++) ca[t] = make_float4(0.f, 0.f, 0.f, 0.f);

    for (int r = 0; r < 4; r++) {
        const int i = blockIdx.x * 32 + w * 4 + r;
        const float4* arow = (const float4*)(adj + ((size_t)b * NN + i) * NN);
        float y0 = 0.f, y1 = 0.f, y2 = 0.f;
#pragma unroll
        for (int t = 0; t < 8; t++) {
            float4 a = arow[t * 32 + L];
            int j = t * 128 + L * 4;
            ca[t].x += a.x; ca[t].y += a.y; ca[t].z += a.z; ca[t].w += a.w;
            y0 += a.x * Xs0[j] + a.y * Xs0[j + 1] + a.z * Xs0[j + 2] + a.w * Xs0[j + 3];
            y1 += a.x * Xs1[j] + a.y * Xs1[j + 1] + a.z * Xs1[j + 2] + a.w * Xs1[j + 3];
            y2 += a.x * Xs2[j] + a.y * Xs2[j + 1] + a.z * Xs2[j + 2] + a.w * Xs2[j + 3];
        }
#pragma unroll
        for (int off = 16; off; off >>= 1) {
            y0 += __shfl_xor_sync(0xffffffffu, y0, off);
            y1 += __shfl_xor_sync(0xffffffffu, y1, off);
            y2 += __shfl_xor_sync(0xffffffffu, y2, off);
        }
        float hA = fmaxf(y0 * w1s[L * 3] + y1 * w1s[L * 3 + 1] + y2 * w1s[L * 3 + 2] + b1s[L], 0.f);
        int L2 = L + 32;
        float hB = fmaxf(y0 * w1s[L2 * 3] + y1 * w1s[L2 * 3 + 1] + y2 * w1s[L2 * 3 + 2] + b1s[L2], 0.f);
        hs[w][L] = hA; hs[w][L2] = hB;
        __syncwarp();
        float p0 = 0.f, p1 = 0.f;
#pragma unroll
        for (int o = 0; o < NH; o++) {
            float hv = hs[w][o];
            p0 += hv * W2t[o * NH + L];
            p1 += hv * W2t[o * NH + L2];
        }
        Pts[L][w * 4 + r]  = p0;
        Pts[L2][w * 4 + r] = p1;
        __syncwarp();
    }
    __syncthreads();

    // coalesced transposed writeback: P1t[b][o][block*32 + i]
    {
        const int i = tid & 31;
        const int ow = tid >> 5;
#pragma unroll
        for (int p = 0; p < 8; p++) {
            int o = p * 8 + ow;
            g_P1t[((size_t)b * NH + o) * NN + blockIdx.x * 32 + i] = Pts[o][i];
        }
    }

    // deterministic in-block column-sum combine
    for (int ws = 0; ws < 8; ws++) {
        if (w == ws) {
#pragma unroll
            for (int t = 0; t < 8; t++) {
                int j = t * 128 + L * 4;
                colp[j]     += ca[t].x;
                colp[j + 1] += ca[t].y;
                colp[j + 2] += ca[t].z;
                colp[j + 3] += ca[t].w;
            }
        }
        __syncthreads();
    }
    for (int idx = tid; idx < NN; idx += 256)
        g_spart[((size_t)b * 32 + blockIdx.x) * NN + idx] = colp[idx];
}

// colsum reduction
__global__ void k_sred()
{
    int b = blockIdx.y;
    int j = blockIdx.x * 256 + threadIdx.x;
    float acc = 0.f;
#pragma unroll
    for (int p = 0; p < 32; p++) acc += g_spart[((size_t)b * 32 + p) * NN + j];
    g_s[b * NN + j] = acc;
}

// ============================================================================
// K2: C = relu(A @ P1 + b2) via mma.sync tf32 (m16n8k8).
// 128 threads (4 warps x 32 rows), BM=128, BN=64, BK=16, double-buffered
// cp.async. XOR-swizzled smem tiles (16B-chunk swizzle: c4 ^= (row>>1)&3).
// ============================================================================
__global__ __launch_bounds__(128) void k_gcn2(
    const float* __restrict__ adj, const float* __restrict__ b2)
{
    __shared__ __align__(16) float As[2][128 * 16];   // 16 KB
    __shared__ __align__(16) float Bs[2][64 * 16];    // 8 KB
    __shared__ float b2s[64];

    const int b = blockIdx.y;
    const int m0 = blockIdx.x * 128;
    const int tid = threadIdx.x;
    const int wid = tid >> 5, L = tid & 31;

    if (tid < 64) b2s[tid] = b2[tid];

    const float* Ab  = adj + ((size_t)b << 20);
    const float* P1b = g_P1t + (size_t)b * NH * NN;

    const uint32_t as_a0 = smem_u32(&As[0][0]);
    const uint32_t bs_a0 = smem_u32(&Bs[0][0]);

    // cp.async assignments
    const int arow = tid >> 2, ac4 = tid & 3;        // A: rows arow+32h, chunk ac4
    const int bn = tid >> 1, bc0 = tid & 1;          // B: row bn, chunks bc0, bc0+2

    auto issue = [&](int kt, int s) {
        const int k0 = kt * 16;
        const uint32_t Ab_s = as_a0 + s * 8192;
        const uint32_t Bb_s = bs_a0 + s * 4096;
#pragma unroll
        for (int h = 0; h < 4; h++) {
            int r = arow + h * 32;
            int c4s = ac4 ^ ((r >> 1) & 3);
            CP16(Ab_s + r * 64 + c4s * 16, Ab + (size_t)(m0 + r) * NN + k0 + ac4 * 4);
        }
        {
            int x = (bn >> 1) & 3;
            CP16(Bb_s + bn * 64 + (bc0 ^ x) * 16, P1b + (size_t)bn * NN + k0 + bc0 * 4);
            int bc1 = bc0 + 2;
            CP16(Bb_s + bn * 64 + (bc1 ^ x) * 16, P1b + (size_t)bn * NN + k0 + bc1 * 4);
        }
        CP_COMMIT();
    };

    // fragment addressing (lane-constant)
    const int gID = L >> 2, tig = L & 3;
    const int x = gID >> 1;                 // swizzle for ALL fragment rows
    // A rows for the two m16 strips
    const int ra0 = wid * 32 + gID;         // strip0 row pair: ra0, ra0+8
    const int ra1 = wid * 32 + 16 + gID;    // strip1 row pair: ra1, ra1+8

    float acc[2][8][4];
#pragma unroll
    for (int s2 = 0; s2 < 2; s2++)
#pragma unroll
        for (int nt = 0; nt < 8; nt++)
#pragma unroll
            for (int q = 0; q < 4; q++) acc[s2][nt][q] = 0.f;

    issue(0, 0);

    for (int kt = 0; kt < 64; kt++) {
        const int s = kt & 1;
        if (kt < 63) {
            issue(kt + 1, s ^ 1);
            asm volatile("cp.async.wait_group 1;" ::: "memory");
        } else {
            asm volatile("cp.async.wait_group 0;" ::: "memory");
        }
        __syncthreads();

        const float* A_s = &As[0][0] + s * 2048;
        const float* B_s = &Bs[0][0] + s * 1024;

#pragma unroll
        for (int ko = 0; ko < 2; ko++) {          // k-halves: cols 0-7, 8-15
            const int ck0 = ko * 2;               // chunk of cols tig
            const int ck1 = ck0 + 1;              // chunk of cols tig+4
            const int o0 = ((ck0 ^ x) << 2) + tig;
            const int o1 = ((ck1 ^ x) << 2) + tig;

            uint32_t a[2][4];
#pragma unroll
            for (int s2 = 0; s2 < 2; s2++) {
                const int r = (s2 == 0) ? ra0 : ra1;
                a[s2][0] = __float_as_uint(A_s[r * 16 + o0]);
                a[s2][1] = __float_as_uint(A_s[(r + 8) * 16 + o0]);
                a[s2][2] = __float_as_uint(A_s[r * 16 + o1]);
                a[s2][3] = __float_as_uint(A_s[(r + 8) * 16 + o1]);
            }
#pragma unroll
            for (int nt = 0; nt < 8; nt++) {
                const int n = nt * 8 + gID;
                uint32_t b0 = __float_as_uint(B_s[n * 16 + o0]);
                uint32_t b1 = __float_as_uint(B_s[n * 16 + o1]);
                mma1688(acc[0][nt], a[0][0], a[0][1], a[0][2], a[0][3], b0, b1);
                mma1688(acc[1][nt], a[1][0], a[1][1], a[1][2], a[1][3], b0, b1);
            }
        }
        __syncthreads();
    }

    // epilogue: C = relu(acc + b2) -> g_P2 row-major
#pragma unroll
    for (int s2 = 0; s2 < 2; s2++) {
        const int R0 = m0 + wid * 32 + s2 * 16 + gID;
        const int R1 = R0 + 8;
        float* d0 = g_P2 + ((size_t)b * NN + R0) * NH;
        float* d1 = g_P2 + ((size_t)b * NN + R1) * NH;
#pragma unroll
        for (int nt = 0; nt < 8; nt++) {
            const int C0 = nt * 8 + tig * 2;
            float2 v0, v1;
            v0.x = fmaxf(acc[s2][nt][0] + b2s[C0], 0.f);
            v0.y = fmaxf(acc[s2][nt][1] + b2s[C0 + 1], 0.f);
            v1.x = fmaxf(acc[s2][nt][2] + b2s[C0], 0.f);
            v1.y = fmaxf(acc[s2][nt][3] + b2s[C0 + 1], 0.f);
            *(float2*)(d0 + C0) = v0;
            *(float2*)(d1 + C0) = v1;
        }
    }
}

// ============================================================================
// crep stage 1: q_part[b][p][o] = sum_{j in part p} s[b][j] * C[b][j][o]
// ============================================================================
__global__ void k_crep1()
{
    __shared__ float red[256];
    const int b = blockIdx.y, p = blockIdx.x;
    const int tid = threadIdx.x;
    const int o = tid & 63, qq = tid >> 6;
    const float* sb = g_s + b * NN + p * 256;
    const float* Cb = g_P2 + (size_t)b * NN * NH + (size_t)p * 256 * NH;
    float acc = 0.f;
    for (int j = qq * 64; j < qq * 64 + 64; j++)
        acc += sb[j] * Cb[(size_t)j * NH + o];
    red[tid] = acc;
    __syncthreads();
    if (qq == 0)
        g_cpart[(b * 4 + p) * 64 + o] = red[o] + red[64 + o] + red[128 + o] + red[192 + o];
}

// crep stage 2: crep[b][n] = (1/N) * (q @ W3^T)[n] + b3[n]
__global__ void k_crep2(const float* __restrict__ w3, const float* __restrict__ b3)
{
    __shared__ float qs[64];
    const int b = blockIdx.x, n = threadIdx.x;
    qs[n] = g_cpart[(b * 4 + 0) * 64 + n] + g_cpart[(b * 4 + 1) * 64 + n]
          + g_cpart[(b * 4 + 2) * 64 + n] + g_cpart[(b * 4 + 3) * 64 + n];
    __syncthreads();
    float acc = 0.f;
    const float* wr = w3 + n * 64;
#pragma unroll
    for (int o = 0; o < 64; o++) acc += qs[o] * wr[o];
    g_crep[b * NH + n] = acc * (1.0f / NN) + b3[n];
}

// LSTM input projections
__global__ void k_xw(const float* __restrict__ wihf, const float* __restrict__ bihf,
                     const float* __restrict__ bhhf,
                     const float* __restrict__ wihb, const float* __restrict__ bihb,
                     const float* __restrict__ bhhb)
{
    __shared__ float cr[64];
    const int t = blockIdx.x;
    const int tid = threadIdx.x;
    if (tid < 64) cr[tid] = g_crep[t * 64 + tid];
    __syncthreads();
    const int g = tid & 127, dir = tid >> 7;
    const float* wih = dir ? wihb : wihf;
    float acc = dir ? (bihb[g] + bhhb[g]) : (bihf[g] + bhhf[g]);
    const float* wg = wih + g * 64;
#pragma unroll
    for (int k = 0; k < 64; k++) acc += cr[k] * wg[k];
    g_xw[dir * 8192 + t * 128 + g] = acc;
}

// ============================================================================
// BiLSTM scan + time encoder + tvec
// ============================================================================
__global__ __launch_bounds__(256) void k_lstm(
    const float* __restrict__ whhf, const float* __restrict__ whhb,
    const float* __restrict__ tew, const float* __restrict__ teb,
    const float* __restrict__ ns1w, const float* __restrict__ ns1b)
{
    __shared__ float whTf[32 * 128], whTb[32 * 128];
    __shared__ float zf[128], zb[128];
    __shared__ float hf[32], cf[32], hb[32], cb[32], sf_[32], sb_[32], tr[64];
    const int tid = threadIdx.x;

    for (int idx = tid; idx < 4096; idx += 256) {
        int k = idx >> 7, g = idx & 127;
        whTf[idx] = whhf[g * 32 + k];
        whTb[idx] = whhb[g * 32 + k];
    }
    if (tid < 32) { hf[tid] = 0.f; cf[tid] = 0.f; hb[tid] = 0.f; cb[tid] = 0.f; sf_[tid] = 0.f; sb_[tid] = 0.f; }
    __syncthreads();

    for (int st = 0; st < 64; st++) {
        if (tid < 128) {
            const int g = tid;
            float z = g_xw[st * 128 + g];
#pragma unroll
            for (int k = 0; k < 32; k++) z += hf[k] * whTf[k * 128 + g];
            zf[g] = z;
        } else {
            const int g = tid - 128;
            float z = g_xw[8192 + (63 - st) * 128 + g];
#pragma unroll
            for (int k = 0; k < 32; k++) z += hb[k] * whTb[k * 128 + g];
            zb[g] = z;
        }
        __syncthreads();
        if (tid < 32) {
            int j = tid;
            float iv = sigm(zf[j]), fv = sigm(zf[32 + j]);
            float gv = tanhf(zf[64 + j]), ov = sigm(zf[96 + j]);
            float c = fv * cf[j] + iv * gv;
            cf[j] = c;
            float h = ov * tanhf(c);
            hf[j] = h; sf_[j] += h;
        } else if (tid >= 128 && tid < 160) {
            int j = tid - 128;
            float iv = sigm(zb[j]), fv = sigm(zb[32 + j]);
            float gv = tanhf(zb[64 + j]), ov = sigm(zb[96 + j]);
            float c = fv * cb[j] + iv * gv;
            cb[j] = c;
            float h = ov * tanhf(c);
            hb[j] = h; sb_[j] += h;
        }
        __syncthreads();
    }

    if (tid < 64) {
        float acc = teb[tid];
        const float* tw = tew + tid * 64;
#pragma unroll
        for (int k = 0; k < 32; k++) acc += (sf_[k] * (1.0f / 64)) * tw[k];
#pragma unroll
        for (int k = 0; k < 32; k++) acc += (sb_[k] * (1.0f / 64)) * tw[32 + k];
        tr[tid] = fmaxf(acc, 0.f);
    }
    __syncthreads();
    if (tid < 64) {
        float acc = ns1b[tid];
        const float* nw = ns1w + tid * 128 + 64;
#pragma unroll
        for (int k = 0; k < 64; k++) acc += tr[k] * nw[k];
        g_tvec[tid] = acc;
    }
}

// ============================================================================
// K3a: E_partials = A[pidx] @ C[pidx]  (split-K x4, SIMT)
// ============================================================================
__global__ __launch_bounds__(256) void k_gcn3(
    const float* __restrict__ adj, const int* __restrict__ pidx)
{
    __shared__ float As[16 * 68];
    __shared__ float Bs[16 * 64];
    const int chunk = pidx[0];
    const float* Ab = adj + ((size_t)chunk << 20);
    const float* Pb = g_P2 + (size_t)chunk * NN * NH;
    const int m0 = blockIdx.x * 64;
    const int kb = blockIdx.y * 256;
    const int tid = threadIdx.x;
    const int tx = tid & 15, ty = tid >> 4;
    const int arow = tid >> 2, akq = tid & 3;
    const int brow = tid >> 4, bc4 = tid & 15;

    float acc[4][4];
#pragma unroll
    for (int i = 0; i < 4; i++)
#pragma unroll
        for (int j = 0; j < 4; j++) acc[i][j] = 0.f;

    for (int kt = 0; kt < 16; kt++) {
        const int k0 = kb + kt * 16;
        float4 a = *(const float4*)(Ab + (size_t)(m0 + arow) * NN + k0 + akq * 4);
        As[(akq * 4 + 0) * 68 + arow] = a.x;
        As[(akq * 4 + 1) * 68 + arow] = a.y;
        As[(akq * 4 + 2) * 68 + arow] = a.z;
        As[(akq * 4 + 3) * 68 + arow] = a.w;
        *(float4*)(Bs + brow * 64 + bc4 * 4) =
            *(const float4*)(Pb + (size_t)(k0 + brow) * NH + bc4 * 4);
        __syncthreads();
#pragma unroll
        for (int kk = 0; kk < 16; kk++) {
            float4 a4 = *(const float4*)(As + kk * 68 + ty * 4);
            float4 b4 = *(const float4*)(Bs + kk * 64 + tx * 4);
            float av[4] = {a4.x, a4.y, a4.z, a4.w};
#pragma unroll
            for (int i = 0; i < 4; i++) {
                acc[i][0] += av[i] * b4.x;
                acc[i][1] += av[i] * b4.y;
                acc[i][2] += av[i] * b4.z;
                acc[i][3] += av[i] * b4.w;
            }
        }
        __syncthreads();
    }
#pragma unroll
    for (int i = 0; i < 4; i++)
#pragma unroll
        for (int j = 0; j < 4; j++)
            g_embp[(size_t)blockIdx.y * (NN * NH) + (m0 + ty * 4 + i) * NH + tx * 4 + j] = acc[i][j];
}

// ============================================================================
// K3b: emb = (E)@W3^T + b3 ; h = relu([emb, tr]@ns1^T + b) ; score = sigmoid
// ============================================================================
__global__ __launch_bounds__(256) void k_score(
    const float* __restrict__ w3, const float* __restrict__ b3,
    const float* __restrict__ ns1w, const float* __restrict__ ns2w,
    const float* __restrict__ ns2b, float* __restrict__ out)
{
    __shared__ float WLt[64 * 64];  // WLt[k][o] = ns1w[o*128 + k]
    __shared__ float W3s[64 * 64];  // W3s[a*64+b] = w3[b*64+a]
    __shared__ float ns2s[64], tvs[64], b3s[64];
    __shared__ float ers[8][64];
    const int tid = threadIdx.x;
    for (int idx = tid; idx < 4096; idx += 256) {
        int k = idx >> 6, o = idx & 63;
        WLt[idx] = ns1w[o * 128 + k];
        W3s[idx] = w3[o * 64 + k];
    }
    if (tid < 64) { ns2s[tid] = ns2w[tid]; tvs[tid] = g_tvec[tid]; b3s[tid] = b3[tid]; }
    __syncthreads();

    const int w = tid >> 5, L = tid & 31;
    const int row = blockIdx.x * 8 + w;
    const int L2 = L + 32;

    // stage 0: raw split-K partial sum (pre-W3)
    ers[w][L] = g_embp[row * NH + L] + g_embp[65536 + row * NH + L]
              + g_embp[131072 + row * NH + L] + g_embp[196608 + row * NH + L];
    ers[w][L2] = g_embp[row * NH + L2] + g_embp[65536 + row * NH + L2]
               + g_embp[131072 + row * NH + L2] + g_embp[196608 + row * NH + L2];
    __syncwarp();

    // stage 1: emb[n] = sum_o raw[o] * w3[n*64+o] + b3[n];  W3s[o*64+n]==w3[n*64+o]
    float e0 = b3s[L], e1 = b3s[L2];
#pragma unroll
    for (int o = 0; o < 64; o++) {
        float rv = ers[w][o];
        e0 += rv * W3s[o * 64 + L];
        e1 += rv * W3s[o * 64 + L2];
    }
    __syncwarp();
    ers[w][L] = e0; ers[w][L2] = e1;
    __syncwarp();

    // stage 2: node scorer
    float a0 = tvs[L], a1 = tvs[L2];
#pragma unroll
    for (int k = 0; k < 64; k++) {
        float ev = ers[w][k];
        a0 += ev * WLt[k * 64 + L];
        a1 += ev * WLt[k * 64 + L2];
    }
    a0 = fmaxf(a0, 0.f);
    a1 = fmaxf(a1, 0.f);
    float p = a0 * ns2s[L] + a1 * ns2s[L2];
#pragma unroll
    for (int off = 16; off; off >>= 1) p += __shfl_xor_sync(0xffffffffu, p, off);
    if (L == 0) out[row] = 1.0f / (1.0f + expf(-(p + ns2b[0])));
}

// ============================================================================
extern "C" void kernel_launch(void* const* d_in, const int* in_sizes, int n_in,
                              void* d_out, int out_size)
{
    (void)in_sizes; (void)n_in; (void)out_size;
    const float* feat  = (const float*)d_in[0];
    const float* adj   = (const float*)d_in[1];
    const float* gc1w  = (const float*)d_in[2];
    const float* gc1b  = (const float*)d_in[3];
    const float* gc2w  = (const float*)d_in[4];
    const float* gc2b  = (const float*)d_in[5];
    const float* gc3w  = (const float*)d_in[6];
    const float* gc3b  = (const float*)d_in[7];
    const float* wihf  = (const float*)d_in[8];
    const float* whhf  = (const float*)d_in[9];
    const float* bihf  = (const float*)d_in[10];
    const float* bhhf  = (const float*)d_in[11];
    const float* wihb  = (const float*)d_in[12];
    const float* whhb  = (const float*)d_in[13];
    const float* bihb  = (const float*)d_in[14];
    const float* bhhb  = (const float*)d_in[15];
    const float* tew   = (const float*)d_in[16];
    const float* teb   = (const float*)d_in[17];
    const float* ns1w  = (const float*)d_in[18];
    const float* ns1b  = (const float*)d_in[19];
    const float* ns2w  = (const float*)d_in[20];
    const float* ns2b  = (const float*)d_in[21];
    const int*   pidx  = (const int*)d_in[23];
    float* out = (float*)d_out;

    k_gcn1<<<dim3(32, 64), 256>>>(feat, adj, gc1w, gc1b, gc2w);
    k_sred<<<dim3(4, 64), 256>>>();
    k_gcn2<<<dim3(8, 64), 128>>>(adj, gc2b);
    k_crep1<<<dim3(4, 64), 256>>>();
    k_crep2<<<64, 64>>>(gc3w, gc3b);
    k_xw<<<64, 256>>>(wihf, bihf, bhhf, wihb, bihb, bhhb);
    k_lstm<<<1, 256>>>(whhf, whhb, tew, teb, ns1w, ns1b);
    k_gcn3<<<dim3(16, 4), 256>>>(adj, pidx);
    k_score<<<128, 256>>>(gc3w, gc3b, ns1w, ns2w, ns2b, out);
}

// round 7
// speedup vs baseline: 2.0155x; 1.2862x over previous
#include <cuda_runtime.h>
#include <math.h>
#include <stdint.h>

#define NB 64
#define NN 1024
#define NF 3
#define NH 64
#define NT 32

// ---------------- scratch (static device memory) ---------------------------
__device__ float g_Xpt[NB * 8 * NN];        // padded X^T [b][8][j]      (2 MB)
__device__ float g_h1t[NB * NH * NN];       // h1 transposed [b][o][j]  (16 MB)
__device__ float g_P2[NB * NN * NH];        // h2 = relu((A@h1)W2^T+b2) (16 MB)
__device__ float g_spart[NB * 8 * NN];      // per-CTA colsum partials   (2 MB)
__device__ float g_s[NB * NN];              // colsum(A) per chunk
__device__ float g_cpart[NB * 4 * NH];      // crep partials
__device__ float g_crep[NB * NH];           // chunk representations
__device__ float g_xw[2 * NB * 4 * NT];     // LSTM input projections
__device__ float g_tvec[NH];                // ns1_right @ time_repr + ns1_b
__device__ float g_embp[4 * NN * NH];       // split-K partials of A_p @ h2_p

__device__ __forceinline__ float sigm(float x) { return 1.0f / (1.0f + expf(-x)); }

#define CP16(dst, src)  asm volatile("cp.async.cg.shared.global [%0], [%1], 16;" :: "r"(dst), "l"(src))
#define CP_COMMIT()     asm volatile("cp.async.commit_group;" ::: "memory")

__device__ __forceinline__ uint32_t smem_u32(const void* p) {
    uint32_t a;
    asm("{ .reg .u64 t; cvta.to.shared.u64 t, %1; cvt.u32.u64 %0, t; }" : "=r"(a) : "l"(p));
    return a;
}

// mma.sync m16n8k8 tf32 (legacy tensor path, baseline PTX, sm_80+)
__device__ __forceinline__ void mma1688(float* c, uint32_t a0, uint32_t a1,
                                        uint32_t a2, uint32_t a3,
                                        uint32_t b0, uint32_t b1) {
    asm volatile(
        "mma.sync.aligned.m16n8k8.row.col.f32.tf32.tf32.f32 "
        "{%0,%1,%2,%3}, {%4,%5,%6,%7}, {%8,%9}, {%0,%1,%2,%3};"
        : "+f"(c[0]), "+f"(c[1]), "+f"(c[2]), "+f"(c[3])
        : "r"(a0), "r"(a1), "r"(a2), "r"(a3), "r"(b0), "r"(b1));
}

// ============================================================================
// k_pre: build padded X^T per chunk: Xpt[b][c][j] = feat[b][j][c], rows 3..7 = 0
// ============================================================================
__global__ void k_pre(const float* __restrict__ feat)
{
    const int b = blockIdx.x;
    const float* fb = feat + (size_t)b * NN * NF;
    float* xp = g_Xpt + (size_t)b * 8 * NN;
    for (int j = threadIdx.x; j < NN; j += 256) {
        xp[j]            = fb[j * 3 + 0];
        xp[NN + j]       = fb[j * 3 + 1];
        xp[2 * NN + j]   = fb[j * 3 + 2];
        xp[3 * NN + j] = 0.f; xp[4 * NN + j] = 0.f; xp[5 * NN + j] = 0.f;
        xp[6 * NN + j] = 0.f; xp[7 * NN + j] = 0.f;
    }
}

// ============================================================================
// k_gemm1: Y = A @ Xp (tensor, BM=128, BN=8), + colsum partials from smem
// tiles, epilogue h1 = relu(Y@W1^T + b1) stored TRANSPOSED to g_h1t[o][j].
// ============================================================================
__global__ __launch_bounds__(128) void k_gemm1(
    const float* __restrict__ adj, const float* __restrict__ w1,
    const float* __restrict__ b1)
{
    __shared__ __align__(16) float As[2][128 * 16];   // 16 KB
    __shared__ __align__(16) float Bs[2][8 * 16];     // 1 KB
    __shared__ float w1s[192], b1s[64];
    __shared__ float Ys[128][4];
    __shared__ __align__(16) float pbuf[32][4][4];    // [rq][c4][4]

    const int b = blockIdx.y;
    const int m0 = blockIdx.x * 128;
    const int tid = threadIdx.x;
    const int wid = tid >> 5, L = tid & 31;

    if (tid < 192) w1s[tid] = w1[tid];
    if (tid < 64)  b1s[tid] = b1[tid];

    const float* Ab = adj + ((size_t)b << 20);
    const float* Xb = g_Xpt + (size_t)b * 8 * NN;

    const uint32_t as_a0 = smem_u32(&As[0][0]);
    const uint32_t bs_a0 = smem_u32(&Bs[0][0]);

    const int arow = tid >> 2, ac4 = tid & 3;

    auto issue = [&](int kt, int s) {
        const int k0 = kt * 16;
        const uint32_t Ab_s = as_a0 + s * 8192;
        const uint32_t Bb_s = bs_a0 + s * 512;
#pragma unroll
        for (int h = 0; h < 4; h++) {
            int r = arow + h * 32;
            int c4s = ac4 ^ ((r >> 1) & 3);
            CP16(Ab_s + r * 64 + c4s * 16, Ab + (size_t)(m0 + r) * NN + k0 + ac4 * 4);
        }
        if (tid < 32) {
            int n = tid >> 2, c4 = tid & 3;
            int c4s = c4 ^ ((n >> 1) & 3);
            CP16(Bb_s + n * 64 + c4s * 16, Xb + (size_t)n * NN + k0 + c4 * 4);
        }
        CP_COMMIT();
    };

    const int gID = L >> 2, tig = L & 3;
    const int x = gID >> 1;
    const int ra0 = wid * 32 + gID;
    const int ra1 = wid * 32 + 16 + gID;

    float acc[2][4];
#pragma unroll
    for (int s2 = 0; s2 < 2; s2++)
#pragma unroll
        for (int q = 0; q < 4; q++) acc[s2][q] = 0.f;

    issue(0, 0);

    for (int kt = 0; kt < 64; kt++) {
        const int s = kt & 1;
        if (kt < 63) {
            issue(kt + 1, s ^ 1);
            asm volatile("cp.async.wait_group 1;" ::: "memory");
        } else {
            asm volatile("cp.async.wait_group 0;" ::: "memory");
        }
        __syncthreads();

        const float* A_s = &As[0][0] + s * 2048;
        const float* B_s = &Bs[0][0] + s * 128;

#pragma unroll
        for (int ko = 0; ko < 2; ko++) {
            const int ck0 = ko * 2, ck1 = ck0 + 1;
            const int o0 = ((ck0 ^ x) << 2) + tig;
            const int o1 = ((ck1 ^ x) << 2) + tig;
            uint32_t b0 = __float_as_uint(B_s[gID * 16 + o0]);
            uint32_t b1f = __float_as_uint(B_s[gID * 16 + o1]);
            {
                uint32_t a0 = __float_as_uint(A_s[ra0 * 16 + o0]);
                uint32_t a1 = __float_as_uint(A_s[(ra0 + 8) * 16 + o0]);
                uint32_t a2 = __float_as_uint(A_s[ra0 * 16 + o1]);
                uint32_t a3 = __float_as_uint(A_s[(ra0 + 8) * 16 + o1]);
                mma1688(acc[0], a0, a1, a2, a3, b0, b1f);
            }
            {
                uint32_t a0 = __float_as_uint(A_s[ra1 * 16 + o0]);
                uint32_t a1 = __float_as_uint(A_s[(ra1 + 8) * 16 + o0]);
                uint32_t a2 = __float_as_uint(A_s[ra1 * 16 + o1]);
                uint32_t a3 = __float_as_uint(A_s[(ra1 + 8) * 16 + o1]);
                mma1688(acc[1], a0, a1, a2, a3, b0, b1f);
            }
        }

        // colsum side-sum of this A tile (128 rows x 16 cols)
        {
            const int c4 = tid & 3, rq = tid >> 2;
            float4 ps = make_float4(0.f, 0.f, 0.f, 0.f);
#pragma unroll
            for (int rr = 0; rr < 4; rr++) {
                int r = rq * 4 + rr;
                int c4s = c4 ^ ((r >> 1) & 3);
                float4 v = *(const float4*)(A_s + r * 16 + c4s * 4);
                ps.x += v.x; ps.y += v.y; ps.z += v.z; ps.w += v.w;
            }
            *(float4*)&pbuf[rq][c4][0] = ps;
        }
        __syncthreads();
        if (tid < 16) {
            const int c4 = tid >> 2, cc = tid & 3;
            float a2 = 0.f;
#pragma unroll
            for (int rq = 0; rq < 32; rq++) a2 += pbuf[rq][c4][cc];
            g_spart[((size_t)b * 8 + blockIdx.x) * NN + kt * 16 + tid] = a2;
        }
        // no trailing sync needed: next iter's top __syncthreads orders pbuf reuse
    }
    __syncthreads();

    // stage Y (cols 0..2) then epilogue h1 = relu(Y@W1^T + b1), transposed store
#pragma unroll
    for (int s2 = 0; s2 < 2; s2++) {
        const int base = wid * 32 + s2 * 16;
        if (tig == 0) {
            Ys[base + gID][0] = acc[s2][0];     Ys[base + gID][1] = acc[s2][1];
            Ys[base + gID + 8][0] = acc[s2][2]; Ys[base + gID + 8][1] = acc[s2][3];
        } else if (tig == 1) {
            Ys[base + gID][2] = acc[s2][0];
            Ys[base + gID + 8][2] = acc[s2][2];
        }
    }
    __syncthreads();
    {
        const float y0 = Ys[tid][0], y1 = Ys[tid][1], y2 = Ys[tid][2];
        float* dst = g_h1t + (size_t)b * NH * NN + m0 + tid;
#pragma unroll
        for (int o = 0; o < 64; o++) {
            float h = fmaxf(y0 * w1s[o * 3] + y1 * w1s[o * 3 + 1]
                          + y2 * w1s[o * 3 + 2] + b1s[o], 0.f);
            dst[(size_t)o * NN] = h;
        }
    }
}

// colsum reduction: 8 partials per chunk
__global__ void k_sred()
{
    int b = blockIdx.y;
    int j = blockIdx.x * 256 + threadIdx.x;
    float acc = 0.f;
#pragma unroll
    for (int p = 0; p < 8; p++) acc += g_spart[((size_t)b * 8 + p) * NN + j];
    g_s[b * NN + j] = acc;
}

// ============================================================================
// k_gemm2: T = A @ h1 (tensor, mainloop = proven R6 code, B = g_h1t);
// epilogue h2 = relu(T @ W2^T + b2) through smem -> g_P2 row-major.
// Manually partitioned 48 KB buffer: [0:6144) mainloop tiles,
// [8192:12288) W2t, epilogue Ts = [0:8192).
// ============================================================================
__global__ __launch_bounds__(128) void k_gemm2(
    const float* __restrict__ adj, const float* __restrict__ w2,
    const float* __restrict__ b2)
{
    __shared__ __align__(16) float smx[12288];    // 48 KB exactly

    float* W2t = smx + 8192;                      // W2t[o*64+n] = w2[n*64+o]
    float* Ts  = smx;                             // epilogue [128][64]

    const int b = blockIdx.y;
    const int m0 = blockIdx.x * 128;
    const int tid = threadIdx.x;
    const int wid = tid >> 5, L = tid & 31;

    for (int idx = tid; idx < 4096; idx += 128) {
        int o = idx >> 6, n = idx & 63;
        W2t[idx] = w2[n * 64 + o];
    }

    const float* Ab  = adj + ((size_t)b << 20);
    const float* H1b = g_h1t + (size_t)b * NH * NN;

    const uint32_t as_a0 = smem_u32(smx);
    const uint32_t bs_a0 = smem_u32(smx + 4096);

    const int arow = tid >> 2, ac4 = tid & 3;
    const int bn = tid >> 1, bc0 = tid & 1;

    auto issue = [&](int kt, int s) {
        const int k0 = kt * 16;
        const uint32_t Ab_s = as_a0 + s * 8192;
        const uint32_t Bb_s = bs_a0 + s * 4096;
#pragma unroll
        for (int h = 0; h < 4; h++) {
            int r = arow + h * 32;
            int c4s = ac4 ^ ((r >> 1) & 3);
            CP16(Ab_s + r * 64 + c4s * 16, Ab + (size_t)(m0 + r) * NN + k0 + ac4 * 4);
        }
        {
            int xs = (bn >> 1) & 3;
            CP16(Bb_s + bn * 64 + (bc0 ^ xs) * 16, H1b + (size_t)bn * NN + k0 + bc0 * 4);
            int bc1 = bc0 + 2;
            CP16(Bb_s + bn * 64 + (bc1 ^ xs) * 16, H1b + (size_t)bn * NN + k0 + bc1 * 4);
        }
        CP_COMMIT();
    };

    const int gID = L >> 2, tig = L & 3;
    const int x = gID >> 1;
    const int ra0 = wid * 32 + gID;
    const int ra1 = wid * 32 + 16 + gID;

    float acc[2][8][4];
#pragma unroll
    for (int s2 = 0; s2 < 2; s2++)
#pragma unroll
        for (int nt = 0; nt < 8; nt++)
#pragma unroll
            for (int q = 0; q < 4; q++) acc[s2][nt][q] = 0.f;

    issue(0, 0);

    for (int kt = 0; kt < 64; kt++) {
        const int s = kt & 1;
        if (kt < 63) {
            issue(kt + 1, s ^ 1);
            asm volatile("cp.async.wait_group 1;" ::: "memory");
        } else {
            asm volatile("cp.async.wait_group 0;" ::: "memory");
        }
        __syncthreads();

        const float* A_s = smx + s * 2048;
        const float* B_s = smx + 4096 + s * 1024;

#pragma unroll
        for (int ko = 0; ko < 2; ko++) {
            const int ck0 = ko * 2, ck1 = ck0 + 1;
            const int o0 = ((ck0 ^ x) << 2) + tig;
            const int o1 = ((ck1 ^ x) << 2) + tig;

            uint32_t a[2][4];
#pragma unroll
            for (int s2 = 0; s2 < 2; s2++) {
                const int r = (s2 == 0) ? ra0 : ra1;
                a[s2][0] = __float_as_uint(A_s[r * 16 + o0]);
                a[s2][1] = __float_as_uint(A_s[(r + 8) * 16 + o0]);
                a[s2][2] = __float_as_uint(A_s[r * 16 + o1]);
                a[s2][3] = __float_as_uint(A_s[(r + 8) * 16 + o1]);
            }
#pragma unroll
            for (int nt = 0; nt < 8; nt++) {
                const int n = nt * 8 + gID;
                uint32_t b0 = __float_as_uint(B_s[n * 16 + o0]);
                uint32_t b1f = __float_as_uint(B_s[n * 16 + o1]);
                mma1688(acc[0][nt], a[0][0], a[0][1], a[0][2], a[0][3], b0, b1f);
                mma1688(acc[1][nt], a[1][0], a[1][1], a[1][2], a[1][3], b0, b1f);
            }
        }
        __syncthreads();
    }

    // stage T fragments -> Ts[128][64]
#pragma unroll
    for (int s2 = 0; s2 < 2; s2++) {
        const int r0 = wid * 32 + s2 * 16 + gID;
#pragma unroll
        for (int nt = 0; nt < 8; nt++) {
            const int C0 = nt * 8 + tig * 2;
            Ts[r0 * 64 + C0]           = acc[s2][nt][0];
            Ts[r0 * 64 + C0 + 1]       = acc[s2][nt][1];
            Ts[(r0 + 8) * 64 + C0]     = acc[s2][nt][2];
            Ts[(r0 + 8) * 64 + C0 + 1] = acc[s2][nt][3];
        }
    }
    __syncthreads();

    // epilogue gemm: h2[r][n] = relu( sum_o Ts[r][o]*W2t[o][n] + b2[n] )
    {
        const int tx = tid & 15, ty = tid >> 4;     // 16 cols grp x 8 row grps
        float4 b2v = *(const float4*)(b2 + tx * 4);
        float acc2[16][4];
#pragma unroll
        for (int i = 0; i < 16; i++)
#pragma unroll
            for (int j = 0; j < 4; j++) acc2[i][j] = 0.f;

#pragma unroll 4
        for (int oc = 0; oc < 16; oc++) {
            float4 w40 = *(const float4*)(W2t + (oc * 4 + 0) * 64 + tx * 4);
            float4 w41 = *(const float4*)(W2t + (oc * 4 + 1) * 64 + tx * 4);
            float4 w42 = *(const float4*)(W2t + (oc * 4 + 2) * 64 + tx * 4);
            float4 w43 = *(const float4*)(W2t + (oc * 4 + 3) * 64 + tx * 4);
#pragma unroll
            for (int i = 0; i < 16; i++) {
                float4 t4 = *(const float4*)(Ts + (ty * 16 + i) * 64 + oc * 4);
                acc2[i][0] += t4.x * w40.x + t4.y * w41.x + t4.z * w42.x + t4.w * w43.x;
                acc2[i][1] += t4.x * w40.y + t4.y * w41.y + t4.z * w42.y + t4.w * w43.y;
                acc2[i][2] += t4.x * w40.z + t4.y * w41.z + t4.z * w42.z + t4.w * w43.z;
                acc2[i][3] += t4.x * w40.w + t4.y * w41.w + t4.z * w42.w + t4.w * w43.w;
            }
        }
#pragma unroll
        for (int i = 0; i < 16; i++) {
            float4 v;
            v.x = fmaxf(acc2[i][0] + b2v.x, 0.f);
            v.y = fmaxf(acc2[i][1] + b2v.y, 0.f);
            v.z = fmaxf(acc2[i][2] + b2v.z, 0.f);
            v.w = fmaxf(acc2[i][3] + b2v.w, 0.f);
            *(float4*)(g_P2 + ((size_t)b * NN + m0 + ty * 16 + i) * NH + tx * 4) = v;
        }
    }
}

// ============================================================================
// crep stage 1: q_part[b][p][o] = sum_{j in part p} s[b][j] * h2[b][j][o]
// ============================================================================
__global__ void k_crep1()
{
    __shared__ float red[256];
    const int b = blockIdx.y, p = blockIdx.x;
    const int tid = threadIdx.x;
    const int o = tid & 63, qq = tid >> 6;
    const float* sb = g_s + b * NN + p * 256;
    const float* Cb = g_P2 + (size_t)b * NN * NH + (size_t)p * 256 * NH;
    float acc = 0.f;
    for (int j = qq * 64; j < qq * 64 + 64; j++)
        acc += sb[j] * Cb[(size_t)j * NH + o];
    red[tid] = acc;
    __syncthreads();
    if (qq == 0)
        g_cpart[(b * 4 + p) * 64 + o] = red[o] + red[64 + o] + red[128 + o] + red[192 + o];
}

// crep stage 2: crep[b][n] = (1/N) * (q @ W3^T)[n] + b3[n]
__global__ void k_crep2(const float* __restrict__ w3, const float* __restrict__ b3)
{
    __shared__ float qs[64];
    const int b = blockIdx.x, n = threadIdx.x;
    qs[n] = g_cpart[(b * 4 + 0) * 64 + n] + g_cpart[(b * 4 + 1) * 64 + n]
          + g_cpart[(b * 4 + 2) * 64 + n] + g_cpart[(b * 4 + 3) * 64 + n];
    __syncthreads();
    float acc = 0.f;
    const float* wr = w3 + n * 64;
#pragma unroll
    for (int o = 0; o < 64; o++) acc += qs[o] * wr[o];
    g_crep[b * NH + n] = acc * (1.0f / NN) + b3[n];
}

// LSTM input projections
__global__ void k_xw(const float* __restrict__ wihf, const float* __restrict__ bihf,
                     const float* __restrict__ bhhf,
                     const float* __restrict__ wihb, const float* __restrict__ bihb,
                     const float* __restrict__ bhhb)
{
    __shared__ float cr[64];
    const int t = blockIdx.x;
    const int tid = threadIdx.x;
    if (tid < 64) cr[tid] = g_crep[t * 64 + tid];
    __syncthreads();
    const int g = tid & 127, dir = tid >> 7;
    const float* wih = dir ? wihb : wihf;
    float acc = dir ? (bihb[g] + bhhb[g]) : (bihf[g] + bhhf[g]);
    const float* wg = wih + g * 64;
#pragma unroll
    for (int k = 0; k < 64; k++) acc += cr[k] * wg[k];
    g_xw[dir * 8192 + t * 128 + g] = acc;
}

// ============================================================================
// BiLSTM scan + time encoder + tvec
// ============================================================================
__global__ __launch_bounds__(256) void k_lstm(
    const float* __restrict__ whhf, const float* __restrict__ whhb,
    const float* __restrict__ tew, const float* __restrict__ teb,
    const float* __restrict__ ns1w, const float* __restrict__ ns1b)
{
    __shared__ float whTf[32 * 128], whTb[32 * 128];
    __shared__ float zf[128], zb[128];
    __shared__ float hf[32], cf[32], hb[32], cb[32], sf_[32], sb_[32], tr[64];
    const int tid = threadIdx.x;

    for (int idx = tid; idx < 4096; idx += 256) {
        int k = idx >> 7, g = idx & 127;
        whTf[idx] = whhf[g * 32 + k];
        whTb[idx] = whhb[g * 32 + k];
    }
    if (tid < 32) { hf[tid] = 0.f; cf[tid] = 0.f; hb[tid] = 0.f; cb[tid] = 0.f; sf_[tid] = 0.f; sb_[tid] = 0.f; }
    __syncthreads();

    for (int st = 0; st < 64; st++) {
        if (tid < 128) {
            const int g = tid;
            float z = g_xw[st * 128 + g];
#pragma unroll
            for (int k = 0; k < 32; k++) z += hf[k] * whTf[k * 128 + g];
            zf[g] = z;
        } else {
            const int g = tid - 128;
            float z = g_xw[8192 + (63 - st) * 128 + g];
#pragma unroll
            for (int k = 0; k < 32; k++) z += hb[k] * whTb[k * 128 + g];
            zb[g] = z;
        }
        __syncthreads();
        if (tid < 32) {
            int j = tid;
            float iv = sigm(zf[j]), fv = sigm(zf[32 + j]);
            float gv = tanhf(zf[64 + j]), ov = sigm(zf[96 + j]);
            float c = fv * cf[j] + iv * gv;
            cf[j] = c;
            float h = ov * tanhf(c);
            hf[j] = h; sf_[j] += h;
        } else if (tid >= 128 && tid < 160) {
            int j = tid - 128;
            float iv = sigm(zb[j]), fv = sigm(zb[32 + j]);
            float gv = tanhf(zb[64 + j]), ov = sigm(zb[96 + j]);
            float c = fv * cb[j] + iv * gv;
            cb[j] = c;
            float h = ov * tanhf(c);
            hb[j] = h; sb_[j] += h;
        }
        __syncthreads();
    }

    if (tid < 64) {
        float acc = teb[tid];
        const float* tw = tew + tid * 64;
#pragma unroll
        for (int k = 0; k < 32; k++) acc += (sf_[k] * (1.0f / 64)) * tw[k];
#pragma unroll
        for (int k = 0; k < 32; k++) acc += (sb_[k] * (1.0f / 64)) * tw[32 + k];
        tr[tid] = fmaxf(acc, 0.f);
    }
    __syncthreads();
    if (tid < 64) {
        float acc = ns1b[tid];
        const float* nw = ns1w + tid * 128 + 64;
#pragma unroll
        for (int k = 0; k < 64; k++) acc += tr[k] * nw[k];
        g_tvec[tid] = acc;
    }
}

// ============================================================================
// K3a: E_partials = A[pidx] @ h2[pidx]  (split-K x4, SIMT)
// ============================================================================
__global__ __launch_bounds__(256) void k_gcn3(
    const float* __restrict__ adj, const int* __restrict__ pidx)
{
    __shared__ float As[16 * 68];
    __shared__ float Bs[16 * 64];
    const int chunk = pidx[0];
    const float* Ab = adj + ((size_t)chunk << 20);
    const float* Pb = g_P2 + (size_t)chunk * NN * NH;
    const int m0 = blockIdx.x * 64;
    const int kb = blockIdx.y * 256;
    const int tid = threadIdx.x;
    const int tx = tid & 15, ty = tid >> 4;
    const int arow = tid >> 2, akq = tid & 3;
    const int brow = tid >> 4, bc4 = tid & 15;

    float acc[4][4];
#pragma unroll
    for (int i = 0; i < 4; i++)
#pragma unroll
        for (int j = 0; j < 4; j++) acc[i][j] = 0.f;

    for (int kt = 0; kt < 16; kt++) {
        const int k0 = kb + kt * 16;
        float4 a = *(const float4*)(Ab + (size_t)(m0 + arow) * NN + k0 + akq * 4);
        As[(akq * 4 + 0) * 68 + arow] = a.x;
        As[(akq * 4 + 1) * 68 + arow] = a.y;
        As[(akq * 4 + 2) * 68 + arow] = a.z;
        As[(akq * 4 + 3) * 68 + arow] = a.w;
        *(float4*)(Bs + brow * 64 + bc4 * 4) =
            *(const float4*)(Pb + (size_t)(k0 + brow) * NH + bc4 * 4);
        __syncthreads();
#pragma unroll
        for (int kk = 0; kk < 16; kk++) {
            float4 a4 = *(const float4*)(As + kk * 68 + ty * 4);
            float4 b4 = *(const float4*)(Bs + kk * 64 + tx * 4);
            float av[4] = {a4.x, a4.y, a4.z, a4.w};
#pragma unroll
            for (int i = 0; i < 4; i++) {
                acc[i][0] += av[i] * b4.x;
                acc[i][1] += av[i] * b4.y;
                acc[i][2] += av[i] * b4.z;
                acc[i][3] += av[i] * b4.w;
            }
        }
        __syncthreads();
    }
#pragma unroll
    for (int i = 0; i < 4; i++)
#pragma unroll
        for (int j = 0; j < 4; j++)
            g_embp[(size_t)blockIdx.y * (NN * NH) + (m0 + ty * 4 + i) * NH + tx * 4 + j] = acc[i][j];
}

// ============================================================================
// K3b: emb = E@W3^T + b3 ; h = relu([emb, tr]@ns1^T + b) ; score = sigmoid
// ============================================================================
__global__ __launch_bounds__(256) void k_score(
    const float* __restrict__ w3, const float* __restrict__ b3,
    const float* __restrict__ ns1w, const float* __restrict__ ns2w,
    const float* __restrict__ ns2b, float* __restrict__ out)
{
    __shared__ float WLt[64 * 64];  // WLt[k][o] = ns1w[o*128 + k]
    __shared__ float W3s[64 * 64];  // W3s[o*64+n] = w3[n*64+o]
    __shared__ float ns2s[64], tvs[64], b3s[64];
    __shared__ float ers[8][64];
    const int tid = threadIdx.x;
    for (int idx = tid; idx < 4096; idx += 256) {
        int k = idx >> 6, o = idx & 63;
        WLt[idx] = ns1w[o * 128 + k];
        W3s[idx] = w3[o * 64 + k];
    }
    if (tid < 64) { ns2s[tid] = ns2w[tid]; tvs[tid] = g_tvec[tid]; b3s[tid] = b3[tid]; }
    __syncthreads();

    const int w = tid >> 5, L = tid & 31;
    const int row = blockIdx.x * 8 + w;
    const int L2 = L + 32;

    ers[w][L] = g_embp[row * NH + L] + g_embp[65536 + row * NH + L]
              + g_embp[131072 + row * NH + L] + g_embp[196608 + row * NH + L];
    ers[w][L2] = g_embp[row * NH + L2] + g_embp[65536 + row * NH + L2]
               + g_embp[131072 + row * NH + L2] + g_embp[196608 + row * NH + L2];
    __syncwarp();

    float e0 = b3s[L], e1 = b3s[L2];
#pragma unroll
    for (int o = 0; o < 64; o++) {
        float rv = ers[w][o];
        e0 += rv * W3s[o * 64 + L];
        e1 += rv * W3s[o * 64 + L2];
    }
    __syncwarp();
    ers[w][L] = e0; ers[w][L2] = e1;
    __syncwarp();

    float a0 = tvs[L], a1 = tvs[L2];
#pragma unroll
    for (int k = 0; k < 64; k++) {
        float ev = ers[w][k];
        a0 += ev * WLt[k * 64 + L];
        a1 += ev * WLt[k * 64 + L2];
    }
    a0 = fmaxf(a0, 0.f);
    a1 = fmaxf(a1, 0.f);
    float p = a0 * ns2s[L] + a1 * ns2s[L2];
#pragma unroll
    for (int off = 16; off; off >>= 1) p += __shfl_xor_sync(0xffffffffu, p, off);
    if (L == 0) out[row] = 1.0f / (1.0f + expf(-(p + ns2b[0])));
}

// ============================================================================
extern "C" void kernel_launch(void* const* d_in, const int* in_sizes, int n_in,
                              void* d_out, int out_size)
{
    (void)in_sizes; (void)n_in; (void)out_size;
    const float* feat  = (const float*)d_in[0];
    const float* adj   = (const float*)d_in[1];
    const float* gc1w  = (const float*)d_in[2];
    const float* gc1b  = (const float*)d_in[3];
    const float* gc2w  = (const float*)d_in[4];
    const float* gc2b  = (const float*)d_in[5];
    const float* gc3w  = (const float*)d_in[6];
    const float* gc3b  = (const float*)d_in[7];
    const float* wihf  = (const float*)d_in[8];
    const float* whhf  = (const float*)d_in[9];
    const float* bihf  = (const float*)d_in[10];
    const float* bhhf  = (const float*)d_in[11];
    const float* wihb  = (const float*)d_in[12];
    const float* whhb  = (const float*)d_in[13];
    const float* bihb  = (const float*)d_in[14];
    const float* bhhb  = (const float*)d_in[15];
    const float* tew   = (const float*)d_in[16];
    const float* teb   = (const float*)d_in[17];
    const float* ns1w  = (const float*)d_in[18];
    const float* ns1b  = (const float*)d_in[19];
    const float* ns2w  = (const float*)d_in[20];
    const float* ns2b  = (const float*)d_in[21];
    const int*   pidx  = (const int*)d_in[23];
    float* out = (float*)d_out;

    k_pre<<<64, 256>>>(feat);
    k_gemm1<<<dim3(8, 64), 128>>>(adj, gc1w, gc1b);
    k_sred<<<dim3(4, 64), 256>>>();
    k_gemm2<<<dim3(8, 64), 128>>>(adj, gc2w, gc2b);
    k_crep1<<<dim3(4, 64), 256>>>();
    k_crep2<<<64, 64>>>(gc3w, gc3b);
    k_xw<<<64, 256>>>(wihf, bihf, bhhf, wihb, bihb, bhhb);
    k_lstm<<<1, 256>>>(whhf, whhb, tew, teb, ns1w, ns1b);
    k_gcn3<<<dim3(16, 4), 256>>>(adj, pidx);
    k_score<<<128, 256>>>(gc3w, gc3b, ns1w, ns2w, ns2b, out);
}